// round 4
// baseline (speedup 1.0000x reference)
#include <cuda_runtime.h>
#include <cuda_fp16.h>

#define D         128
#define DV        32
#define MAXN      100000
#define CHUNK     256
#define MAXCHUNKS 25088
#define GS        130        // Wt smem stride
#define ASTR      132        // A-tile smem stride

// Scratch (allocation-free per harness rules)
__device__ __half g_hW[(size_t)MAXN * D];            // 25.6 MB h @ W^T fp16
__device__ float  g_pfirst[(size_t)MAXCHUNKS * D];   // leading-run partials
__device__ float  g_plast[(size_t)MAXCHUNKS * D];    // trailing-run partials
__device__ unsigned char g_flag[MAXN];               // row finalized?

// ---------------------------------------------------------------------------
// Kernel 1: zero flags only (no full-out zero needed anymore)
// ---------------------------------------------------------------------------
__global__ void zero_flags_kernel(int nflag4) {
    int i = blockIdx.x * blockDim.x + threadIdx.x;
    if (i < nflag4) reinterpret_cast<int*>(g_flag)[i] = 0;
}

// ---------------------------------------------------------------------------
// Kernel 2: hW = h @ W^T (fp32 FFMA2 compute, fp16 store)
// Block: 64 rows x 128 cols, 256 threads; thread = 4 rows x 4 col-pairs.
// W staged TRANSPOSED so adjacent output cols are contiguous -> LDS.64 pairs.
// ---------------------------------------------------------------------------
__global__ void __launch_bounds__(256) gemm_hw_kernel(
    const float* __restrict__ h,
    const float* __restrict__ W,
    int n) {
    extern __shared__ float smem[];
    float* Wt = smem;                  // [128][GS]
    float* As = smem + 128 * GS;       // [64][ASTR]

    int t = threadIdx.x;

    const float4* W4 = reinterpret_cast<const float4*>(W);
    for (int idx = t; idx < 128 * 32; idx += 256) {
        int j = idx >> 5, k4 = idx & 31;
        float4 w = W4[idx];
        Wt[(k4 * 4 + 0) * GS + j] = w.x;
        Wt[(k4 * 4 + 1) * GS + j] = w.y;
        Wt[(k4 * 4 + 2) * GS + j] = w.z;
        Wt[(k4 * 4 + 3) * GS + j] = w.w;
    }

    int row0 = blockIdx.x * 64;
    const float4* H4 = reinterpret_cast<const float4*>(h);
    for (int idx = t; idx < 64 * 32; idx += 256) {
        int r = idx >> 5, k4 = idx & 31;
        int gr = row0 + r;
        float4 a = (gr < n) ? H4[(size_t)gr * 32 + k4]
                            : make_float4(0.f, 0.f, 0.f, 0.f);
        *reinterpret_cast<float4*>(&As[r * ASTR + k4 * 4]) = a;
    }
    __syncthreads();

    int tx = t & 15;
    int ty = t >> 4;

    unsigned long long acc[4][4];
#pragma unroll
    for (int i = 0; i < 4; i++)
#pragma unroll
        for (int p = 0; p < 4; p++) acc[i][p] = 0ull;

    const float* Ap = As + (ty * 4) * ASTR;

#pragma unroll 4
    for (int k = 0; k < 128; k++) {
        const float* Wk = Wt + k * GS + 2 * tx;
        unsigned long long w[4];
#pragma unroll
        for (int p = 0; p < 4; p++)
            w[p] = *reinterpret_cast<const unsigned long long*>(Wk + 32 * p);
#pragma unroll
        for (int i = 0; i < 4; i++) {
            float a = Ap[i * ASTR + k];
            unsigned long long aa;
            asm("mov.b64 %0, {%1, %1};" : "=l"(aa) : "f"(a));
#pragma unroll
            for (int p = 0; p < 4; p++)
                asm("fma.rn.f32x2 %0, %1, %2, %3;"
                    : "=l"(acc[i][p]) : "l"(aa), "l"(w[p]), "l"(acc[i][p]));
        }
    }

#pragma unroll
    for (int i = 0; i < 4; i++) {
        int gr = row0 + ty * 4 + i;
        if (gr < n) {
            __half* op = g_hW + (size_t)gr * D;
#pragma unroll
            for (int p = 0; p < 4; p++) {
                float lo, hi;
                asm("mov.b64 {%0, %1}, %2;" : "=f"(lo), "=f"(hi) : "l"(acc[i][p]));
                *reinterpret_cast<__half2*>(op + 2 * tx + 32 * p) =
                    __floats2half2_rn(lo, hi);
            }
        }
    }
}

// ---------------------------------------------------------------------------
// Kernel 3: SpMM — warp per CHUNK edges, software-pipelined 8-edge batches.
// Owned rows: direct STG relu(acc+b) + flag. Boundary runs: plain-store
// partials to g_pfirst / g_plast (NO atomics, NO pre-zeroed out).
// ---------------------------------------------------------------------------
__device__ __forceinline__ void finalize_row(float* __restrict__ out, int row,
                                             float4 a, float4 bv, int lane) {
    float4 r;
    r.x = fmaxf(a.x + bv.x, 0.f);
    r.y = fmaxf(a.y + bv.y, 0.f);
    r.z = fmaxf(a.z + bv.z, 0.f);
    r.w = fmaxf(a.w + bv.w, 0.f);
    *reinterpret_cast<float4*>(out + (size_t)row * D + lane * 4) = r;
    if (lane == 0) g_flag[row] = 1;
}

__global__ void __launch_bounds__(256) spmm_kernel(
    const int*   __restrict__ rows,
    const int*   __restrict__ cols,
    const float* __restrict__ vals,
    const float* __restrict__ b,
    float*       __restrict__ out,
    int E) {
    int lane = threadIdx.x & 31;
    int c    = blockIdx.x * (blockDim.x >> 5) + (threadIdx.x >> 5);  // chunk id
    int start = c * CHUNK;
    if (start >= E) return;
    int end = min(E, start + CHUNK);

    int  first_row    = __ldg(rows + start);
    bool first_shared = (start > 0) && (__ldg(rows + start - 1) == first_row);
    bool last_shared  = (end < E)   && (__ldg(rows + end) == __ldg(rows + end - 1));

    const float4 bv = reinterpret_cast<const float4*>(b)[lane];
    const uint2* __restrict__ hw2 = reinterpret_cast<const uint2*>(g_hW);

    float4 acc = make_float4(0.f, 0.f, 0.f, 0.f);
    int cur = first_row;

#define FLUSH_MID()                                                            \
    do {                                                                       \
        if (cur == first_row && first_shared)                                  \
            *reinterpret_cast<float4*>(g_pfirst + (size_t)c * D + lane * 4) = acc; \
        else                                                                   \
            finalize_row(out, cur, acc, bv, lane);                             \
    } while (0)

#define PROC_EDGE(rr, vv, raw)                                                 \
    do {                                                                       \
        if ((rr) != cur) {                                                     \
            FLUSH_MID();                                                       \
            acc = make_float4(0.f, 0.f, 0.f, 0.f);                             \
            cur = (rr);                                                        \
        }                                                                      \
        float2 f0 = __half22float2(*reinterpret_cast<const __half2*>(&(raw).x)); \
        float2 f1 = __half22float2(*reinterpret_cast<const __half2*>(&(raw).y)); \
        acc.x = fmaf((vv), f0.x, acc.x);                                       \
        acc.y = fmaf((vv), f0.y, acc.y);                                       \
        acc.z = fmaf((vv), f1.x, acc.z);                                       \
        acc.w = fmaf((vv), f1.y, acc.w);                                       \
    } while (0)

    int nb = (end - start) >> 3;          // full 8-edge batches
    int e  = start;

    if (nb > 0) {
        int4   ra = *reinterpret_cast<const int4*>(rows + e);
        int4   rb_ = *reinterpret_cast<const int4*>(rows + e + 4);
        int4   ca = *reinterpret_cast<const int4*>(cols + e);
        int4   cb = *reinterpret_cast<const int4*>(cols + e + 4);
        float4 va = *reinterpret_cast<const float4*>(vals + e);
        float4 vb = *reinterpret_cast<const float4*>(vals + e + 4);

        for (int i = 0; i < nb; ++i) {
            // 1. issue all 8 gathers for current batch (MLP 8)
            uint2 g0 = hw2[(size_t)ca.x * DV + lane];
            uint2 g1 = hw2[(size_t)ca.y * DV + lane];
            uint2 g2 = hw2[(size_t)ca.z * DV + lane];
            uint2 g3 = hw2[(size_t)ca.w * DV + lane];
            uint2 g4 = hw2[(size_t)cb.x * DV + lane];
            uint2 g5 = hw2[(size_t)cb.y * DV + lane];
            uint2 g6 = hw2[(size_t)cb.z * DV + lane];
            uint2 g7 = hw2[(size_t)cb.w * DV + lane];

            // 2. prefetch next batch's indices (overlaps gather latency)
            int en = e + 8;
            int ep = (i + 1 < nb) ? en : start;   // in-bounds aligned dummy
            int4   nra = *reinterpret_cast<const int4*>(rows + ep);
            int4   nrb = *reinterpret_cast<const int4*>(rows + ep + 4);
            int4   nca = *reinterpret_cast<const int4*>(cols + ep);
            int4   ncb = *reinterpret_cast<const int4*>(cols + ep + 4);
            float4 nva = *reinterpret_cast<const float4*>(vals + ep);
            float4 nvb = *reinterpret_cast<const float4*>(vals + ep + 4);

            // 3. consume current batch
            PROC_EDGE(ra.x, va.x, g0);
            PROC_EDGE(ra.y, va.y, g1);
            PROC_EDGE(ra.z, va.z, g2);
            PROC_EDGE(ra.w, va.w, g3);
            PROC_EDGE(rb_.x, vb.x, g4);
            PROC_EDGE(rb_.y, vb.y, g5);
            PROC_EDGE(rb_.z, vb.z, g6);
            PROC_EDGE(rb_.w, vb.w, g7);

            ra = nra; rb_ = nrb; ca = nca; cb = ncb; va = nva; vb = nvb;
            e = en;
        }
    }
    // scalar tail
    for (; e < end; ++e) {
        int   r  = __ldg(rows + e);
        int   cc = __ldg(cols + e);
        float v  = __ldg(vals + e);
        uint2 raw = hw2[(size_t)cc * DV + lane];
        PROC_EDGE(r, v, raw);
    }

    // end flush
    if (cur == first_row && first_shared) {
        *reinterpret_cast<float4*>(g_pfirst + (size_t)c * D + lane * 4) = acc;
    } else if (last_shared) {
        *reinterpret_cast<float4*>(g_plast + (size_t)c * D + lane * 4) = acc;
    } else {
        finalize_row(out, cur, acc, bv, lane);
    }
#undef PROC_EDGE
#undef FLUSH_MID
}

// ---------------------------------------------------------------------------
// Kernel 4: combine — one warp per chunk; owner chunks sum the partial chain
// for their trailing shared row and finalize it.
// ---------------------------------------------------------------------------
__global__ void __launch_bounds__(256) combine_kernel(
    const int*   __restrict__ rows,
    const float* __restrict__ b,
    float*       __restrict__ out,
    int E) {
    int lane = threadIdx.x & 31;
    int c    = blockIdx.x * 8 + (threadIdx.x >> 5);
    int nchunks = (E + CHUNK - 1) / CHUNK;
    if (c >= nchunks) return;
    int start = c * CHUNK;
    int end   = min(E, start + CHUNK);
    if (end >= E) return;                                  // last chunk
    int r = __ldg(rows + end - 1);
    if (__ldg(rows + end) != r) return;                    // !last_shared
    int fr = __ldg(rows + start);
    bool fs = (start > 0) && (__ldg(rows + start - 1) == fr);
    if (fs && fr == r) return;                             // not the owner

    float4 tot = *reinterpret_cast<const float4*>(g_plast + (size_t)c * D + lane * 4);
    for (int d = c + 1; d < nchunks; ++d) {
        float4 pf = *reinterpret_cast<const float4*>(g_pfirst + (size_t)d * D + lane * 4);
        tot.x += pf.x; tot.y += pf.y; tot.z += pf.z; tot.w += pf.w;
        int dend = min(E, (d + 1) * CHUNK);
        if (__ldg(rows + dend - 1) != r) break;            // run ends inside d
        if (dend >= E || __ldg(rows + dend) != r) break;   // run ends at d's end
    }

    float4 bv = reinterpret_cast<const float4*>(b)[lane];
    float4 o;
    o.x = fmaxf(tot.x + bv.x, 0.f);
    o.y = fmaxf(tot.y + bv.y, 0.f);
    o.z = fmaxf(tot.z + bv.z, 0.f);
    o.w = fmaxf(tot.w + bv.w, 0.f);
    *reinterpret_cast<float4*>(out + (size_t)r * D + lane * 4) = o;
    if (lane == 0) g_flag[r] = 1;
}

// ---------------------------------------------------------------------------
// Kernel 5: fill — relu(b) for rows with no edges (flag==0). Ballot-compacted.
// ---------------------------------------------------------------------------
__global__ void __launch_bounds__(256) fill_kernel(
    const float* __restrict__ b,
    float*       __restrict__ out,
    int n) {
    int lane = threadIdx.x & 31;
    int base = (blockIdx.x * 8 + (threadIdx.x >> 5)) * 32;
    if (base >= n) return;
    int row = base + lane;
    bool empty = (row < n) && (g_flag[row] == 0);
    unsigned m = __ballot_sync(0xffffffff, empty);
    if (!m) return;
    float4 bv = reinterpret_cast<const float4*>(b)[lane];
    float4 rb;
    rb.x = fmaxf(bv.x, 0.f); rb.y = fmaxf(bv.y, 0.f);
    rb.z = fmaxf(bv.z, 0.f); rb.w = fmaxf(bv.w, 0.f);
    while (m) {
        int j = __ffs(m) - 1; m &= m - 1;
        *reinterpret_cast<float4*>(out + (size_t)(base + j) * D + lane * 4) = rb;
    }
}

// ---------------------------------------------------------------------------
extern "C" void kernel_launch(void* const* d_in, const int* in_sizes, int n_in,
                              void* d_out, int out_size) {
    const int*   rows = (const int*)  d_in[0];
    const int*   cols = (const int*)  d_in[1];
    const float* vals = (const float*)d_in[2];
    const float* h    = (const float*)d_in[3];
    const float* W    = (const float*)d_in[4];
    const float* b    = (const float*)d_in[5];
    float*       out  = (float*)d_out;

    int E = in_sizes[0];
    int n = in_sizes[3] / D;
    if (n > MAXN) n = MAXN;

    // 1. zero flags (tiny)
    int nflag4 = (n + 3) / 4;
    zero_flags_kernel<<<(nflag4 + 255) / 256, 256>>>(nflag4);

    // 2. hW = h @ W^T (fp16)
    const int smem_bytes = (128 * GS + 64 * ASTR) * sizeof(float);  // ~98 KB
    cudaFuncSetAttribute(gemm_hw_kernel,
                         cudaFuncAttributeMaxDynamicSharedMemorySize, smem_bytes);
    gemm_hw_kernel<<<(n + 63) / 64, 256, smem_bytes>>>(h, W, n);

    // 3. SpMM -> out (owned rows fused bias+relu; boundary runs -> partials)
    int nchunks = (E + CHUNK - 1) / CHUNK;
    spmm_kernel<<<(nchunks + 7) / 8, 256>>>(rows, cols, vals, b, out, E);

    // 4. combine boundary chains
    combine_kernel<<<(nchunks + 7) / 8, 256>>>(rows, b, out, E);

    // 5. fill empty rows
    int nwarps = (n + 31) / 32;
    fill_kernel<<<(nwarps + 7) / 8, 256>>>(b, out, n);
}

// round 6
// speedup vs baseline: 1.5489x; 1.5489x over previous
#include <cuda_runtime.h>
#include <cuda_fp16.h>
#include <cstdint>

#define D         128
#define DV        32
#define MAXN      100000
#define CHUNK     256
#define MAXCHUNKS 25088
#define AS        136        // fp16 smem stride (conflict-free for ldmatrix)

// Scratch (allocation-free per harness rules)
__device__ __half g_hW[(size_t)MAXN * D];            // 25.6 MB h @ W^T fp16
__device__ float  g_pfirst[(size_t)MAXCHUNKS * D];   // leading-run partials
__device__ float  g_plast[(size_t)MAXCHUNKS * D];    // trailing-run partials
__device__ unsigned char g_flag[MAXN];               // row finalized?

// ---------------------------------------------------------------------------
// Kernel 1: zero flags
// ---------------------------------------------------------------------------
__global__ void zero_flags_kernel(int nflag4) {
    int i = blockIdx.x * blockDim.x + threadIdx.x;
    if (i < nflag4) reinterpret_cast<int*>(g_flag)[i] = 0;
}

// ---------------------------------------------------------------------------
// Kernel 2: hW = h @ W^T via fp16 tensor cores (fp32 accumulate, fp16 store)
// Block: 128 rows x 128 cols, 8 warps; warp = 16 rows x full 128 cols.
// ---------------------------------------------------------------------------
__global__ void __launch_bounds__(256) gemm_tc_kernel(
    const float* __restrict__ h,
    const float* __restrict__ W,
    int n) {
    extern __shared__ __half smem[];
    __half* Asm = smem;               // [128][AS]  h tile fp16
    __half* Wsm = smem + 128 * AS;    // [128][AS]  W fp16 (row j, col k)

    int t = threadIdx.x;

    // Stage W -> fp16 smem (row-major [j][k])
    const float4* W4 = reinterpret_cast<const float4*>(W);
    for (int idx = t; idx < 128 * 32; idx += 256) {
        int r = idx >> 5, c4 = idx & 31;
        float4 w = W4[idx];
        __half2 lo = __floats2half2_rn(w.x, w.y);
        __half2 hi = __floats2half2_rn(w.z, w.w);
        uint2 pk = make_uint2(*reinterpret_cast<uint32_t*>(&lo),
                              *reinterpret_cast<uint32_t*>(&hi));
        *reinterpret_cast<uint2*>(Wsm + r * AS + c4 * 4) = pk;
    }

    // Stage h tile -> fp16 smem
    int row0 = blockIdx.x * 128;
    const float4* H4 = reinterpret_cast<const float4*>(h);
    for (int idx = t; idx < 128 * 32; idx += 256) {
        int r = idx >> 5, c4 = idx & 31;
        int gr = row0 + r;
        float4 a = (gr < n) ? H4[(size_t)gr * 32 + c4]
                            : make_float4(0.f, 0.f, 0.f, 0.f);
        __half2 lo = __floats2half2_rn(a.x, a.y);
        __half2 hi = __floats2half2_rn(a.z, a.w);
        uint2 pk = make_uint2(*reinterpret_cast<uint32_t*>(&lo),
                              *reinterpret_cast<uint32_t*>(&hi));
        *reinterpret_cast<uint2*>(Asm + r * AS + c4 * 4) = pk;
    }
    __syncthreads();

    int warp = t >> 5, lane = t & 31;
    int m0 = warp * 16;

    float acc[16][4];
#pragma unroll
    for (int nt = 0; nt < 16; nt++)
#pragma unroll
        for (int q = 0; q < 4; q++) acc[nt][q] = 0.f;

#pragma unroll
    for (int ks = 0; ks < 8; ks++) {
        int k0 = ks * 16;
        // A fragment: ldmatrix.x4  (rows m0+(lane&15), col k0 + (lane>>4)*8)
        uint32_t a0, a1, a2, a3;
        {
            int r = m0 + (lane & 15);
            int c = k0 + ((lane >> 4) << 3);
            uint32_t addr = (uint32_t)__cvta_generic_to_shared(Asm + r * AS + c);
            asm volatile(
                "ldmatrix.sync.aligned.m8n8.x4.shared.b16 {%0,%1,%2,%3}, [%4];"
                : "=r"(a0), "=r"(a1), "=r"(a2), "=r"(a3) : "r"(addr));
        }
#pragma unroll
        for (int nt = 0; nt < 16; nt++) {
            // B fragment: ldmatrix.x2 (W rows nt*8+(lane&7), cols k0 / k0+8)
            uint32_t b0, b1;
            {
                int r = nt * 8 + (lane & 7);
                int c = k0 + (((lane >> 3) & 1) << 3);
                uint32_t addr = (uint32_t)__cvta_generic_to_shared(Wsm + r * AS + c);
                asm volatile(
                    "ldmatrix.sync.aligned.m8n8.x2.shared.b16 {%0,%1}, [%2];"
                    : "=r"(b0), "=r"(b1) : "r"(addr));
            }
            asm volatile(
                "mma.sync.aligned.m16n8k16.row.col.f32.f16.f16.f32 "
                "{%0,%1,%2,%3}, {%4,%5,%6,%7}, {%8,%9}, {%0,%1,%2,%3};"
                : "+f"(acc[nt][0]), "+f"(acc[nt][1]),
                  "+f"(acc[nt][2]), "+f"(acc[nt][3])
                : "r"(a0), "r"(a1), "r"(a2), "r"(a3), "r"(b0), "r"(b1));
        }
    }

    // Store fp16: c0,c1 -> row g col 2*tg ; c2,c3 -> row g+8
    int g  = lane >> 2;
    int tg = lane & 3;
    int gr0 = row0 + m0 + g;
    int gr1 = gr0 + 8;
#pragma unroll
    for (int nt = 0; nt < 16; nt++) {
        int col = nt * 8 + 2 * tg;
        if (gr0 < n)
            *reinterpret_cast<__half2*>(g_hW + (size_t)gr0 * D + col) =
                __floats2half2_rn(acc[nt][0], acc[nt][1]);
        if (gr1 < n)
            *reinterpret_cast<__half2*>(g_hW + (size_t)gr1 * D + col) =
                __floats2half2_rn(acc[nt][2], acc[nt][3]);
    }
}

// ---------------------------------------------------------------------------
// Kernel 3: SpMM — warp per CHUNK edges, 4-edge batches (R2-proven loop).
// Owned rows: STG relu(acc+b) + flag. Boundary runs: partials (no atomics).
// ---------------------------------------------------------------------------
__device__ __forceinline__ void finalize_row(float* __restrict__ out, int row,
                                             float4 a, float4 bv, int lane) {
    float4 r;
    r.x = fmaxf(a.x + bv.x, 0.f);
    r.y = fmaxf(a.y + bv.y, 0.f);
    r.z = fmaxf(a.z + bv.z, 0.f);
    r.w = fmaxf(a.w + bv.w, 0.f);
    *reinterpret_cast<float4*>(out + (size_t)row * D + lane * 4) = r;
    if (lane == 0) g_flag[row] = 1;
}

__device__ __forceinline__ float4 gather4(const uint2* __restrict__ hw2,
                                          int c, int lane) {
    uint2 raw = hw2[(size_t)c * DV + lane];
    float2 f0 = __half22float2(*reinterpret_cast<const __half2*>(&raw.x));
    float2 f1 = __half22float2(*reinterpret_cast<const __half2*>(&raw.y));
    return make_float4(f0.x, f0.y, f1.x, f1.y);
}

__global__ void __launch_bounds__(256) spmm_kernel(
    const int*   __restrict__ rows,
    const int*   __restrict__ cols,
    const float* __restrict__ vals,
    const float* __restrict__ b,
    float*       __restrict__ out,
    int E) {
    int lane = threadIdx.x & 31;
    int c    = blockIdx.x * (blockDim.x >> 5) + (threadIdx.x >> 5);
    int start = c * CHUNK;
    if (start >= E) return;
    int end = min(E, start + CHUNK);

    int  first_row    = __ldg(rows + start);
    bool first_shared = (start > 0) && (__ldg(rows + start - 1) == first_row);
    bool last_shared  = (end < E)   && (__ldg(rows + end) == __ldg(rows + end - 1));

    const float4 bv = reinterpret_cast<const float4*>(b)[lane];
    const uint2* __restrict__ hw2 = reinterpret_cast<const uint2*>(g_hW);

    float4 acc = make_float4(0.f, 0.f, 0.f, 0.f);
    int cur = first_row;

#define FLUSH_MID()                                                            \
    do {                                                                       \
        if (cur == first_row && first_shared)                                  \
            *reinterpret_cast<float4*>(g_pfirst + (size_t)c * D + lane * 4) = acc; \
        else                                                                   \
            finalize_row(out, cur, acc, bv, lane);                             \
    } while (0)

#define PROC_EDGE(rr, vv, gg)                                                  \
    do {                                                                       \
        if ((rr) != cur) {                                                     \
            FLUSH_MID();                                                       \
            acc = make_float4(0.f, 0.f, 0.f, 0.f);                             \
            cur = (rr);                                                        \
        }                                                                      \
        acc.x = fmaf((vv), (gg).x, acc.x);                                     \
        acc.y = fmaf((vv), (gg).y, acc.y);                                     \
        acc.z = fmaf((vv), (gg).z, acc.z);                                     \
        acc.w = fmaf((vv), (gg).w, acc.w);                                     \
    } while (0)

    int e = start;
    for (; e + 4 <= end; e += 4) {
        int4   r4 = *reinterpret_cast<const int4*>(rows + e);
        int4   c4 = *reinterpret_cast<const int4*>(cols + e);
        float4 v4 = *reinterpret_cast<const float4*>(vals + e);

        float4 g0 = gather4(hw2, c4.x, lane);
        float4 g1 = gather4(hw2, c4.y, lane);
        float4 g2 = gather4(hw2, c4.z, lane);
        float4 g3 = gather4(hw2, c4.w, lane);

        PROC_EDGE(r4.x, v4.x, g0);
        PROC_EDGE(r4.y, v4.y, g1);
        PROC_EDGE(r4.z, v4.z, g2);
        PROC_EDGE(r4.w, v4.w, g3);
    }
    for (; e < end; ++e) {
        int   r  = __ldg(rows + e);
        int   cc = __ldg(cols + e);
        float v  = __ldg(vals + e);
        float4 g = gather4(hw2, cc, lane);
        PROC_EDGE(r, v, g);
    }

    // end flush
    if (cur == first_row && first_shared) {
        *reinterpret_cast<float4*>(g_pfirst + (size_t)c * D + lane * 4) = acc;
    } else if (last_shared) {
        *reinterpret_cast<float4*>(g_plast + (size_t)c * D + lane * 4) = acc;
    } else {
        finalize_row(out, cur, acc, bv, lane);
    }
#undef PROC_EDGE
#undef FLUSH_MID
}

// ---------------------------------------------------------------------------
// Kernel 4: combine — owner chunk sums the partial chain, finalizes its row.
// ---------------------------------------------------------------------------
__global__ void __launch_bounds__(256) combine_kernel(
    const int*   __restrict__ rows,
    const float* __restrict__ b,
    float*       __restrict__ out,
    int E) {
    int lane = threadIdx.x & 31;
    int c    = blockIdx.x * 8 + (threadIdx.x >> 5);
    int nchunks = (E + CHUNK - 1) / CHUNK;
    if (c >= nchunks) return;
    int start = c * CHUNK;
    int end   = min(E, start + CHUNK);
    if (end >= E) return;
    int r = __ldg(rows + end - 1);
    if (__ldg(rows + end) != r) return;
    int fr = __ldg(rows + start);
    bool fs = (start > 0) && (__ldg(rows + start - 1) == fr);
    if (fs && fr == r) return;   // not the owner

    float4 tot = *reinterpret_cast<const float4*>(g_plast + (size_t)c * D + lane * 4);
    for (int d = c + 1; d < nchunks; ++d) {
        float4 pf = *reinterpret_cast<const float4*>(g_pfirst + (size_t)d * D + lane * 4);
        tot.x += pf.x; tot.y += pf.y; tot.z += pf.z; tot.w += pf.w;
        int dend = min(E, (d + 1) * CHUNK);
        if (__ldg(rows + dend - 1) != r) break;
        if (dend >= E || __ldg(rows + dend) != r) break;
    }

    float4 bv = reinterpret_cast<const float4*>(b)[lane];
    float4 o;
    o.x = fmaxf(tot.x + bv.x, 0.f);
    o.y = fmaxf(tot.y + bv.y, 0.f);
    o.z = fmaxf(tot.z + bv.z, 0.f);
    o.w = fmaxf(tot.w + bv.w, 0.f);
    *reinterpret_cast<float4*>(out + (size_t)r * D + lane * 4) = o;
    if (lane == 0) g_flag[r] = 1;
}

// ---------------------------------------------------------------------------
// Kernel 5: fill — relu(b) for rows with no edges. Ballot-compacted.
// ---------------------------------------------------------------------------
__global__ void __launch_bounds__(256) fill_kernel(
    const float* __restrict__ b,
    float*       __restrict__ out,
    int n) {
    int lane = threadIdx.x & 31;
    int base = (blockIdx.x * 8 + (threadIdx.x >> 5)) * 32;
    if (base >= n) return;
    int row = base + lane;
    bool empty = (row < n) && (g_flag[row] == 0);
    unsigned m = __ballot_sync(0xffffffff, empty);
    if (!m) return;
    float4 bv = reinterpret_cast<const float4*>(b)[lane];
    float4 rb;
    rb.x = fmaxf(bv.x, 0.f); rb.y = fmaxf(bv.y, 0.f);
    rb.z = fmaxf(bv.z, 0.f); rb.w = fmaxf(bv.w, 0.f);
    while (m) {
        int j = __ffs(m) - 1; m &= m - 1;
        *reinterpret_cast<float4*>(out + (size_t)(base + j) * D + lane * 4) = rb;
    }
}

// ---------------------------------------------------------------------------
extern "C" void kernel_launch(void* const* d_in, const int* in_sizes, int n_in,
                              void* d_out, int out_size) {
    const int*   rows = (const int*)  d_in[0];
    const int*   cols = (const int*)  d_in[1];
    const float* vals = (const float*)d_in[2];
    const float* h    = (const float*)d_in[3];
    const float* W    = (const float*)d_in[4];
    const float* b    = (const float*)d_in[5];
    float*       out  = (float*)d_out;

    int E = in_sizes[0];
    int n = in_sizes[3] / D;
    if (n > MAXN) n = MAXN;

    // 1. zero flags
    int nflag4 = (n + 3) / 4;
    zero_flags_kernel<<<(nflag4 + 255) / 256, 256>>>(nflag4);

    // 2. hW = h @ W^T via tensor cores
    const int smem_bytes = 2 * 128 * AS * sizeof(__half);   // 69,632 B
    cudaFuncSetAttribute(gemm_tc_kernel,
                         cudaFuncAttributeMaxDynamicSharedMemorySize, smem_bytes);
    gemm_tc_kernel<<<(n + 127) / 128, 256, smem_bytes>>>(h, W, n);

    // 3. SpMM -> out
    int nchunks = (E + CHUNK - 1) / CHUNK;
    spmm_kernel<<<(nchunks + 7) / 8, 256>>>(rows, cols, vals, b, out, E);

    // 4. combine boundary chains
    combine_kernel<<<(nchunks + 7) / 8, 256>>>(rows, b, out, E);

    // 5. fill empty rows
    int nwarps = (n + 31) / 32;
    fill_kernel<<<(nwarps + 7) / 8, 256>>>(b, out, n);
}